// round 9
// baseline (speedup 1.0000x reference)
#include <cuda_runtime.h>
#include <cuda_bf16.h>
#include <cstdint>

// Problem constants
#define NB   4
#define LSEQ 2048
#define EQ   512
#define ET   512
#define NH   8
#define EH   64
#define NF   8

__device__ float g_qkv [(size_t)NB * LSEQ * 3 * ET];   // [b, s, 1536]
__device__ float g_attn[(size_t)NB * LSEQ * ET];       // [b, s, 512]
__device__ float g_wall[(size_t)ET * NF * ET];         // [512, 4096]

#define NEGINF (-1e30f)

__device__ __forceinline__ uint32_t tf32(float x) {
    uint32_t r;
    asm("cvt.rna.tf32.f32 %0, %1;" : "=r"(r) : "f"(x));
    return r;
}

__device__ __forceinline__ void mma_tf32(float* c,
    uint32_t a0, uint32_t a1, uint32_t a2, uint32_t a3,
    uint32_t b0, uint32_t b1)
{
    asm volatile(
        "mma.sync.aligned.m16n8k8.row.col.f32.tf32.tf32.f32 "
        "{%0,%1,%2,%3}, {%4,%5,%6,%7}, {%8,%9}, {%0,%1,%2,%3};"
        : "+f"(c[0]), "+f"(c[1]), "+f"(c[2]), "+f"(c[3])
        : "r"(a0), "r"(a1), "r"(a2), "r"(a3), "r"(b0), "r"(b1));
}

// ---------------------------------------------------------------------------
// tf32 GEMM v2: 128x128x16 block, 128 threads (4 warps, 2x2), warp tile 64x64.
// Per k8: 32 LDS words / 32 mma per thread -> LDS no longer binding.
// ---------------------------------------------------------------------------
template<bool REMAP>
__global__ __launch_bounds__(128) void tgemm_v2(
    const float* __restrict__ A, const float* __restrict__ B,
    const float* __restrict__ bias, float* __restrict__ C,
    int M, int N, int K, int bias_mask)
{
    __shared__ uint32_t As[16][132];   // [k][m], tf32 bits
    __shared__ uint32_t Bs[16][132];   // [k][n], tf32 bits

    const int tid  = threadIdx.x;
    const int lane = tid & 31;
    const int wid  = tid >> 5;
    const int wm   = wid >> 1;          // 0..1
    const int wn   = wid & 1;           // 0..1
    const int g    = lane >> 2;         // 0..7
    const int qq   = lane & 3;          // 0..3
    const int rowBase = blockIdx.y * 128;
    const int colBase = blockIdx.x * 128;

    // A staging: each thread owns one full row (16 cols)
    const float* Aptr = A + (size_t)(rowBase + tid) * K;
    // B staging: bRow = tid>>3 (0..15), bCol = (tid&7)*16
    const int bRow = tid >> 3;
    const int bCol = (tid & 7) * 16;
    const float* Bptr = B + (size_t)bRow * N + colBase + bCol;

    float4 av[4], bv[4];
    #pragma unroll
    for (int j = 0; j < 4; j++) av[j] = *(const float4*)(Aptr + j * 4);
    #pragma unroll
    for (int j = 0; j < 4; j++) bv[j] = *(const float4*)(Bptr + j * 4);

    float acc[4][8][4] = {};   // [mt][nt][frag]

    for (int k0 = 0; k0 < K; k0 += 16) {
        // stage regs -> smem (tf32)
        #pragma unroll
        for (int j = 0; j < 4; j++) {
            const float* p = (const float*)&av[j];
            As[j * 4 + 0][tid] = tf32(p[0]);
            As[j * 4 + 1][tid] = tf32(p[1]);
            As[j * 4 + 2][tid] = tf32(p[2]);
            As[j * 4 + 3][tid] = tf32(p[3]);
            uint4 t;
            const float* q = (const float*)&bv[j];
            t.x = tf32(q[0]); t.y = tf32(q[1]); t.z = tf32(q[2]); t.w = tf32(q[3]);
            *(uint4*)&Bs[bRow][bCol + j * 4] = t;
        }
        __syncthreads();

        // prefetch next slab
        if (k0 + 16 < K) {
            #pragma unroll
            for (int j = 0; j < 4; j++) av[j] = *(const float4*)(Aptr + k0 + 16 + j * 4);
            #pragma unroll
            for (int j = 0; j < 4; j++) bv[j] = *(const float4*)(Bptr + (size_t)(k0 + 16) * N + j * 4);
        }

        #pragma unroll
        for (int k8 = 0; k8 < 16; k8 += 8) {
            uint32_t af[4][4], bf[8][2];
            #pragma unroll
            for (int mt = 0; mt < 4; mt++) {
                int r = wm * 64 + mt * 16 + g;
                af[mt][0] = As[k8 + qq    ][r];
                af[mt][1] = As[k8 + qq    ][r + 8];
                af[mt][2] = As[k8 + qq + 4][r];
                af[mt][3] = As[k8 + qq + 4][r + 8];
            }
            #pragma unroll
            for (int nt = 0; nt < 8; nt++) {
                int n = wn * 64 + nt * 8 + g;
                bf[nt][0] = Bs[k8 + qq    ][n];
                bf[nt][1] = Bs[k8 + qq + 4][n];
            }
            #pragma unroll
            for (int mt = 0; mt < 4; mt++)
                #pragma unroll
                for (int nt = 0; nt < 8; nt++)
                    mma_tf32(acc[mt][nt], af[mt][0], af[mt][1], af[mt][2], af[mt][3],
                             bf[nt][0], bf[nt][1]);
        }
        __syncthreads();
    }

    // epilogue
    #pragma unroll
    for (int mt = 0; mt < 4; mt++) {
        #pragma unroll
        for (int nt = 0; nt < 8; nt++) {
            int row = rowBase + wm * 64 + mt * 16 + g;
            int col = colBase + wn * 64 + nt * 8 + 2 * qq;
            float bx = bias[col & bias_mask];
            float by = bias[(col + 1) & bias_mask];
            float2 v0 = { acc[mt][nt][0] + bx, acc[mt][nt][1] + by };
            float2 v1 = { acc[mt][nt][2] + bx, acc[mt][nt][3] + by };
            size_t i0, i1;
            if (REMAP) {
                int n = col >> 9, e = col & 511;
                int b0i = row >> 11, s0i = row & 2047;
                i0 = (((size_t)(b0i * NF + n) * LSEQ + s0i) * ET) + e;
                int b1i = (row + 8) >> 11, s1i = (row + 8) & 2047;
                i1 = (((size_t)(b1i * NF + n) * LSEQ + s1i) * ET) + e;
            } else {
                i0 = (size_t)row * N + col;
                i1 = (size_t)(row + 8) * N + col;
            }
            *(float2*)&C[i0] = v0;
            *(float2*)&C[i1] = v1;
        }
    }
}

// ---------------------------------------------------------------------------
// Flash attention v2: Q frags preloaded to regs; register softmax with
// shfl + cross-warp smem combine; 3 barriers/kt. 256 threads, 8 warps.
// Warp (wm=wid>>1 rows 16, wn=wid&1 cols 32) of the 64x64 S tile.
// ---------------------------------------------------------------------------
__global__ __launch_bounds__(256) void flash_attn_v2(float* __restrict__ attn)
{
    extern __shared__ float sm[];
    float* Qs   = sm;                  // [64][68]
    float* Ks   = Qs + 64 * 68;        // [64][68]
    float* Vs   = Ks + 64 * 68;        // [64][72]
    float* Ss   = Vs + 64 * 72;        // [64][68] P (tf32 bits)
    float* mrow = Ss + 64 * 68;        // 64
    float* lrow = mrow + 64;           // 64
    float* wmax = lrow + 64;           // [2][64]
    float* wsum = wmax + 128;          // [2][64]

    const int qt  = blockIdx.x;
    const int h   = blockIdx.y;
    const int b   = blockIdx.z;
    const int tid = threadIdx.x;
    const int lane = tid & 31;
    const int wid  = tid >> 5;
    const int wm   = wid >> 1;         // 0..3
    const int wn   = wid & 1;          // 0..1
    const int g    = lane >> 2;        // 0..7
    const int qq   = lane & 3;         // 0..3
    const int q0   = qt * 64;
    const int r0   = wm * 16 + g;
    const int r1   = r0 + 8;

    // Load Q tile (tf32)
    for (int i = tid; i < 1024; i += 256) {
        int r = i >> 4, c4 = (i & 15) * 4;
        float4 v = *(const float4*)&g_qkv[((size_t)(b * LSEQ + q0 + r)) * 1536 + h * 64 + c4];
        uint32_t* dst = (uint32_t*)&Qs[r * 68 + c4];
        dst[0] = tf32(v.x); dst[1] = tf32(v.y); dst[2] = tf32(v.z); dst[3] = tf32(v.w);
    }
    if (tid < 64) { mrow[tid] = NEGINF; lrow[tid] = 0.f; }
    __syncthreads();

    // Preload Q fragments (invariant across kt)
    uint32_t qf[8][4];
    #pragma unroll
    for (int k8 = 0; k8 < 8; k8++) {
        int kb = k8 * 8;
        qf[k8][0] = __float_as_uint(Qs[r0 * 68 + kb + qq]);
        qf[k8][1] = __float_as_uint(Qs[r1 * 68 + kb + qq]);
        qf[k8][2] = __float_as_uint(Qs[r0 * 68 + kb + qq + 4]);
        qf[k8][3] = __float_as_uint(Qs[r1 * 68 + kb + qq + 4]);
    }

    float acc[4][4] = {};

    for (int kt = 0; kt <= qt; kt++) {
        const int k0 = kt * 64;
        __syncthreads();   // B0: prev PV done before overwriting Ks/Vs
        for (int i = tid; i < 1024; i += 256) {
            int r = i >> 4, c4 = (i & 15) * 4;
            size_t base = ((size_t)(b * LSEQ + k0 + r)) * 1536 + h * 64 + c4;
            float4 kv = *(const float4*)&g_qkv[base + 512];
            float4 vv = *(const float4*)&g_qkv[base + 1024];
            uint32_t* dk = (uint32_t*)&Ks[r * 68 + c4];
            dk[0] = tf32(kv.x); dk[1] = tf32(kv.y); dk[2] = tf32(kv.z); dk[3] = tf32(kv.w);
            uint32_t* dv = (uint32_t*)&Vs[r * 72 + c4];
            dv[0] = tf32(vv.x); dv[1] = tf32(vv.y); dv[2] = tf32(vv.z); dv[3] = tf32(vv.w);
        }
        __syncthreads();   // B1: staging visible

        // S = Q @ K^T (regs)
        float s[4][4] = {};
        #pragma unroll
        for (int k8 = 0; k8 < 8; k8++) {
            int kb = k8 * 8;
            #pragma unroll
            for (int nt = 0; nt < 4; nt++) {
                int n = wn * 32 + nt * 8 + g;
                uint32_t b0 = __float_as_uint(Ks[n * 68 + kb + qq]);
                uint32_t b1 = __float_as_uint(Ks[n * 68 + kb + qq + 4]);
                mma_tf32(s[nt], qf[k8][0], qf[k8][1], qf[k8][2], qf[k8][3], b0, b1);
            }
        }
        // scale + causal mask in regs
        {
            const bool diag = (kt == qt);
            #pragma unroll
            for (int nt = 0; nt < 4; nt++) {
                int col = wn * 32 + nt * 8 + 2 * qq;
                s[nt][0] *= 0.125f; s[nt][1] *= 0.125f;
                s[nt][2] *= 0.125f; s[nt][3] *= 0.125f;
                if (diag) {
                    if (col     > r0) s[nt][0] = NEGINF;
                    if (col + 1 > r0) s[nt][1] = NEGINF;
                    if (col     > r1) s[nt][2] = NEGINF;
                    if (col + 1 > r1) s[nt][3] = NEGINF;
                }
            }
        }
        // warp-level row max (over this warp's 32 cols)
        float m_a = NEGINF, m_b = NEGINF;
        #pragma unroll
        for (int nt = 0; nt < 4; nt++) {
            m_a = fmaxf(m_a, fmaxf(s[nt][0], s[nt][1]));
            m_b = fmaxf(m_b, fmaxf(s[nt][2], s[nt][3]));
        }
        m_a = fmaxf(m_a, __shfl_xor_sync(0xffffffffu, m_a, 1));
        m_a = fmaxf(m_a, __shfl_xor_sync(0xffffffffu, m_a, 2));
        m_b = fmaxf(m_b, __shfl_xor_sync(0xffffffffu, m_b, 1));
        m_b = fmaxf(m_b, __shfl_xor_sync(0xffffffffu, m_b, 2));
        if (qq == 0) { wmax[wn * 64 + r0] = m_a; wmax[wn * 64 + r1] = m_b; }
        __syncthreads();   // B2

        const float mx_a = fmaxf(fmaxf(wmax[r0], wmax[64 + r0]), mrow[r0]);
        const float mx_b = fmaxf(fmaxf(wmax[r1], wmax[64 + r1]), mrow[r1]);
        const float sf_a = __expf(mrow[r0] - mx_a);
        const float sf_b = __expf(mrow[r1] - mx_b);

        // exp in regs, partial sums, write P (tf32) to smem
        float sum_a = 0.f, sum_b = 0.f;
        #pragma unroll
        for (int nt = 0; nt < 4; nt++) {
            int col = wn * 32 + nt * 8 + 2 * qq;
            float p0 = __expf(s[nt][0] - mx_a);
            float p1 = __expf(s[nt][1] - mx_a);
            float p2 = __expf(s[nt][2] - mx_b);
            float p3 = __expf(s[nt][3] - mx_b);
            sum_a += p0 + p1;
            sum_b += p2 + p3;
            Ss[r0 * 68 + col    ] = __uint_as_float(tf32(p0));
            Ss[r0 * 68 + col + 1] = __uint_as_float(tf32(p1));
            Ss[r1 * 68 + col    ] = __uint_as_float(tf32(p2));
            Ss[r1 * 68 + col + 1] = __uint_as_float(tf32(p3));
        }
        sum_a += __shfl_xor_sync(0xffffffffu, sum_a, 1);
        sum_a += __shfl_xor_sync(0xffffffffu, sum_a, 2);
        sum_b += __shfl_xor_sync(0xffffffffu, sum_b, 1);
        sum_b += __shfl_xor_sync(0xffffffffu, sum_b, 2);
        if (qq == 0) { wsum[wn * 64 + r0] = sum_a; wsum[wn * 64 + r1] = sum_b; }
        __syncthreads();   // B3: P + wsum visible

        if (wn == 0 && qq == 0) {
            lrow[r0] = lrow[r0] * sf_a + wsum[r0] + wsum[64 + r0];
            mrow[r0] = mx_a;
            lrow[r1] = lrow[r1] * sf_b + wsum[r1] + wsum[64 + r1];
            mrow[r1] = mx_b;
        }

        // rescale acc, PV mma
        #pragma unroll
        for (int nt = 0; nt < 4; nt++) {
            acc[nt][0] *= sf_a; acc[nt][1] *= sf_a;
            acc[nt][2] *= sf_b; acc[nt][3] *= sf_b;
        }
        #pragma unroll
        for (int k8 = 0; k8 < 8; k8++) {
            int kb = k8 * 8;
            uint32_t a0 = __float_as_uint(Ss[r0 * 68 + kb + qq]);
            uint32_t a1 = __float_as_uint(Ss[r1 * 68 + kb + qq]);
            uint32_t a2 = __float_as_uint(Ss[r0 * 68 + kb + qq + 4]);
            uint32_t a3 = __float_as_uint(Ss[r1 * 68 + kb + qq + 4]);
            #pragma unroll
            for (int nt = 0; nt < 4; nt++) {
                int n = wn * 32 + nt * 8 + g;
                uint32_t b0 = __float_as_uint(Vs[(kb + qq    ) * 72 + n]);
                uint32_t b1 = __float_as_uint(Vs[(kb + qq + 4) * 72 + n]);
                mma_tf32(acc[nt], a0, a1, a2, a3, b0, b1);
            }
        }
    }
    __syncthreads();   // lrow updates visible

    {
        float inv0 = 1.f / lrow[r0];
        float inv1 = 1.f / lrow[r1];
        #pragma unroll
        for (int nt = 0; nt < 4; nt++) {
            int col = wn * 32 + nt * 8 + 2 * qq;
            float2 v0 = { acc[nt][0] * inv0, acc[nt][1] * inv0 };
            float2 v1 = { acc[nt][2] * inv1, acc[nt][3] * inv1 };
            *(float2*)&attn[((size_t)(b * LSEQ + q0 + r0)) * ET + h * 64 + col] = v0;
            *(float2*)&attn[((size_t)(b * LSEQ + q0 + r1)) * ET + h * 64 + col] = v1;
        }
    }
}

// ---------------------------------------------------------------------------
// Weight chain: W_all[h*64+d, n*512+e] = ((I + A_h)^{n+1} @ Wo_h)[d, e]
// ---------------------------------------------------------------------------
__global__ __launch_bounds__(256) void chain_kernel(
    const float* __restrict__ Xi, const float* __restrict__ Wo,
    float* __restrict__ wall)
{
    __shared__ float Bs[64][65];
    __shared__ float Ps[2][64][65];

    const int e0 = blockIdx.x * 64;
    const int h  = blockIdx.y;
    const int tid = threadIdx.x;
    const int tx = tid & 15;
    const int ty = tid >> 4;

    for (int i = tid; i < 64 * 64; i += 256) {
        int r = i >> 6, c = i & 63;
        float v = Xi[h * 4096 + r * 64 + c] - Xi[h * 4096 + c * 64 + r];
        if (r == c) v += 1.f;
        Bs[r][c] = v;
    }
    for (int i = tid; i < 64 * 64; i += 256) {
        int r = i >> 6, c = i & 63;
        Ps[0][r][c] = Wo[(size_t)(h * 64 + r) * EQ + e0 + c];
    }
    __syncthreads();

    int cur = 0;
    for (int m = 0; m < NF; m++) {
        float t[4][4] = {};
        #pragma unroll
        for (int d = 0; d < 64; d++) {
            float a[4], bv[4];
            #pragma unroll
            for (int i = 0; i < 4; i++) a[i]  = Bs[ty * 4 + i][d];
            #pragma unroll
            for (int j = 0; j < 4; j++) bv[j] = Ps[cur][d][tx * 4 + j];
            #pragma unroll
            for (int i = 0; i < 4; i++)
                #pragma unroll
                for (int j = 0; j < 4; j++)
                    t[i][j] += a[i] * bv[j];
        }
        #pragma unroll
        for (int i = 0; i < 4; i++) {
            int r = ty * 4 + i;
            #pragma unroll
            for (int j = 0; j < 4; j++) {
                int c = tx * 4 + j;
                Ps[1 - cur][r][c] = t[i][j];
                wall[(size_t)(h * 64 + r) * (NF * ET) + m * ET + e0 + c] = t[i][j];
            }
        }
        cur ^= 1;
        __syncthreads();
    }
}

// ---------------------------------------------------------------------------
// Launcher
// ---------------------------------------------------------------------------
extern "C" void kernel_launch(void* const* d_in, const int* in_sizes, int n_in,
                              void* d_out, int out_size)
{
    const float* query = (const float*)d_in[0];
    const float* Wqkv  = (const float*)d_in[3];
    const float* bqkv  = (const float*)d_in[4];
    const float* Wo    = (const float*)d_in[5];
    const float* bo    = (const float*)d_in[6];
    const float* Xi    = (const float*)d_in[7];
    float* out = (float*)d_out;

    float *pqkv = nullptr, *pattn = nullptr, *pwall = nullptr;
    cudaGetSymbolAddress((void**)&pqkv,  g_qkv);
    cudaGetSymbolAddress((void**)&pattn, g_attn);
    cudaGetSymbolAddress((void**)&pwall, g_wall);

    // Qs + Ks + Vs + Ss + mrow + lrow + wmax(128) + wsum(128)
    const int flash_smem = (64 * 68 * 3 + 64 * 72 + 2 * 64 + 2 * 128) * (int)sizeof(float);
    cudaFuncSetAttribute(flash_attn_v2,
                         cudaFuncAttributeMaxDynamicSharedMemorySize, flash_smem);

    // 1) QKV projection
    {
        dim3 grid((3 * ET) / 128, (NB * LSEQ) / 128);
        tgemm_v2<false><<<grid, 128>>>(query, Wqkv, bqkv, pqkv,
                                       NB * LSEQ, 3 * ET, EQ, 0x7fffffff);
    }
    // 2) Attention
    {
        dim3 grid(LSEQ / 64, NH, NB);
        flash_attn_v2<<<grid, 256, flash_smem>>>(pattn);
    }
    // 3) Weight chain
    {
        dim3 grid(EQ / 64, NH);
        chain_kernel<<<grid, 256>>>(Xi, Wo, pwall);
    }
    // 4) Fused forecast+output GEMM
    {
        dim3 grid((NF * ET) / 128, (NB * LSEQ) / 128);
        tgemm_v2<true><<<grid, 128>>>(pattn, pwall, bo, out,
                                      NB * LSEQ, NF * ET, ET, 511);
    }
}

// round 12
// speedup vs baseline: 1.3956x; 1.3956x over previous
#include <cuda_runtime.h>
#include <cuda_bf16.h>
#include <cstdint>

// Problem constants
#define NB   4
#define LSEQ 2048
#define EQ   512
#define ET   512
#define NH   8
#define EH   64
#define NF   8

__device__ float g_qkv [(size_t)NB * LSEQ * 3 * ET];   // [b, s, 1536]
__device__ float g_attn[(size_t)NB * LSEQ * ET];       // [b, s, 512]
__device__ float g_wall[(size_t)ET * NF * ET];         // [512, 4096]

#define NEGINF (-1e30f)

__device__ __forceinline__ uint32_t tf32(float x) {
    uint32_t r;
    asm("cvt.rna.tf32.f32 %0, %1;" : "=r"(r) : "f"(x));
    return r;
}

__device__ __forceinline__ void mma_tf32(float* c,
    uint32_t a0, uint32_t a1, uint32_t a2, uint32_t a3,
    uint32_t b0, uint32_t b1)
{
    asm volatile(
        "mma.sync.aligned.m16n8k8.row.col.f32.tf32.tf32.f32 "
        "{%0,%1,%2,%3}, {%4,%5,%6,%7}, {%8,%9}, {%0,%1,%2,%3};"
        : "+f"(c[0]), "+f"(c[1]), "+f"(c[2]), "+f"(c[3])
        : "r"(a0), "r"(a1), "r"(a2), "r"(a3), "r"(b0), "r"(b1));
}

// ---------------------------------------------------------------------------
// tf32 GEMM, double-buffered smem: 128x128x16 block, 256 threads (8 warps,
// 2x4), warp tile 64x32 (the R6 operating point: 124 regs, 2 CTA/SM).
// Per iter: LDG next slab -> mma on buf p -> cvt+STS into buf 1-p -> 1 bar.
// ---------------------------------------------------------------------------
template<bool REMAP>
__global__ __launch_bounds__(256) void tgemm_db(
    const float* __restrict__ A, const float* __restrict__ B,
    const float* __restrict__ bias, float* __restrict__ C,
    int M, int N, int K, int bias_mask)
{
    __shared__ uint32_t As[2][128][20];   // [buf][m][k] tf32 bits, pad 20
    __shared__ uint32_t Bs[2][16][136];   // [buf][k][n] tf32 bits, pad 136

    const int tid  = threadIdx.x;
    const int lane = tid & 31;
    const int wid  = tid >> 5;
    const int wm   = wid >> 2;         // 0..1
    const int wn   = wid & 3;          // 0..3
    const int g    = lane >> 2;        // 0..7
    const int qq   = lane & 3;         // 0..3
    const int rowBase = blockIdx.y * 128;
    const int colBase = blockIdx.x * 128;

    const int aRow = tid >> 2;         // 0..63
    const int aCol = (tid & 3) * 4;    // 0,4,8,12
    const int bRow = tid >> 5;         // 0..7
    const int bCol = (tid & 31) * 4;   // 0..124

    const float* Aptr = A + (size_t)(rowBase + aRow) * K + aCol;
    const float* Bptr = B + (size_t)bRow * N + colBase + bCol;

    float4 a0v = *(const float4*)(Aptr);
    float4 a1v = *(const float4*)(Aptr + (size_t)64 * K);
    float4 b0v = *(const float4*)(Bptr);
    float4 b1v = *(const float4*)(Bptr + (size_t)8 * N);

    // stage slab 0 into buffer 0
    {
        uint4 t;
        t.x = tf32(a0v.x); t.y = tf32(a0v.y); t.z = tf32(a0v.z); t.w = tf32(a0v.w);
        *(uint4*)&As[0][aRow][aCol] = t;
        t.x = tf32(a1v.x); t.y = tf32(a1v.y); t.z = tf32(a1v.z); t.w = tf32(a1v.w);
        *(uint4*)&As[0][64 + aRow][aCol] = t;
        t.x = tf32(b0v.x); t.y = tf32(b0v.y); t.z = tf32(b0v.z); t.w = tf32(b0v.w);
        *(uint4*)&Bs[0][bRow][bCol] = t;
        t.x = tf32(b1v.x); t.y = tf32(b1v.y); t.z = tf32(b1v.z); t.w = tf32(b1v.w);
        *(uint4*)&Bs[0][bRow + 8][bCol] = t;
    }
    __syncthreads();

    float acc[4][4][4] = {};   // [mt][nt][frag]

    for (int k0 = 0; k0 < K; k0 += 16) {
        const int p = (k0 >> 4) & 1;
        const bool more = (k0 + 16 < K);

        // prefetch next slab into regs (latency hidden behind mma below)
        if (more) {
            a0v = *(const float4*)(Aptr + k0 + 16);
            a1v = *(const float4*)(Aptr + (size_t)64 * K + k0 + 16);
            b0v = *(const float4*)(Bptr + (size_t)(k0 + 16) * N);
            b1v = *(const float4*)(Bptr + (size_t)(k0 + 24) * N);
        }

        // compute on buffer p
        #pragma unroll
        for (int k8 = 0; k8 < 16; k8 += 8) {
            uint32_t af[4][4], bf[4][2];
            #pragma unroll
            for (int mt = 0; mt < 4; mt++) {
                int r = wm * 64 + mt * 16 + g;
                af[mt][0] = As[p][r    ][k8 + qq];
                af[mt][1] = As[p][r + 8][k8 + qq];
                af[mt][2] = As[p][r    ][k8 + qq + 4];
                af[mt][3] = As[p][r + 8][k8 + qq + 4];
            }
            #pragma unroll
            for (int nt = 0; nt < 4; nt++) {
                int n = wn * 32 + nt * 8 + g;
                bf[nt][0] = Bs[p][k8 + qq    ][n];
                bf[nt][1] = Bs[p][k8 + qq + 4][n];
            }
            #pragma unroll
            for (int mt = 0; mt < 4; mt++)
                #pragma unroll
                for (int nt = 0; nt < 4; nt++)
                    mma_tf32(acc[mt][nt], af[mt][0], af[mt][1], af[mt][2], af[mt][3],
                             bf[nt][0], bf[nt][1]);
        }

        // stage prefetched slab into the other buffer (overlaps mma drain)
        if (more) {
            uint4 t;
            t.x = tf32(a0v.x); t.y = tf32(a0v.y); t.z = tf32(a0v.z); t.w = tf32(a0v.w);
            *(uint4*)&As[1 - p][aRow][aCol] = t;
            t.x = tf32(a1v.x); t.y = tf32(a1v.y); t.z = tf32(a1v.z); t.w = tf32(a1v.w);
            *(uint4*)&As[1 - p][64 + aRow][aCol] = t;
            t.x = tf32(b0v.x); t.y = tf32(b0v.y); t.z = tf32(b0v.z); t.w = tf32(b0v.w);
            *(uint4*)&Bs[1 - p][bRow][bCol] = t;
            t.x = tf32(b1v.x); t.y = tf32(b1v.y); t.z = tf32(b1v.z); t.w = tf32(b1v.w);
            *(uint4*)&Bs[1 - p][bRow + 8][bCol] = t;
        }
        __syncthreads();
    }

    // epilogue: per frag, two float2 stores (rows r and r+8)
    #pragma unroll
    for (int mt = 0; mt < 4; mt++) {
        #pragma unroll
        for (int nt = 0; nt < 4; nt++) {
            int row = rowBase + wm * 64 + mt * 16 + g;
            int col = colBase + wn * 32 + nt * 8 + 2 * qq;
            float bx = bias[col & bias_mask];
            float by = bias[(col + 1) & bias_mask];
            float2 v0 = { acc[mt][nt][0] + bx, acc[mt][nt][1] + by };
            float2 v1 = { acc[mt][nt][2] + bx, acc[mt][nt][3] + by };
            size_t i0, i1;
            if (REMAP) {
                int n = col >> 9, e = col & 511;
                int b0i = row >> 11, s0i = row & 2047;
                i0 = (((size_t)(b0i * NF + n) * LSEQ + s0i) * ET) + e;
                int b1i = (row + 8) >> 11, s1i = (row + 8) & 2047;
                i1 = (((size_t)(b1i * NF + n) * LSEQ + s1i) * ET) + e;
            } else {
                i0 = (size_t)row * N + col;
                i1 = (size_t)(row + 8) * N + col;
            }
            *(float2*)&C[i0] = v0;
            *(float2*)&C[i1] = v1;
        }
    }
}

// ---------------------------------------------------------------------------
// Causal flash attention with tf32 mma (R6 version, measured good).
// One block per (q_tile=64, head, batch). 256 threads, 8 warps.
// ---------------------------------------------------------------------------
__global__ __launch_bounds__(256) void flash_attn_tf32(float* __restrict__ attn)
{
    extern __shared__ float sm[];
    float* Qs   = sm;                  // [64][68]
    float* Ks   = Qs + 64 * 68;        // [64][68]
    float* Vs   = Ks + 64 * 68;        // [64][72]
    float* Ss   = Vs + 64 * 72;        // [64][68]
    float* mrow = Ss + 64 * 68;        // 64
    float* lrow = mrow + 64;           // 64
    float* srow = lrow + 64;           // 64

    const int qt  = blockIdx.x;
    const int h   = blockIdx.y;
    const int b   = blockIdx.z;
    const int tid = threadIdx.x;
    const int lane = tid & 31;
    const int wid  = tid >> 5;
    const int wm   = wid >> 1;         // 0..3
    const int wn   = wid & 1;          // 0..1
    const int g    = lane >> 2;        // 0..7
    const int qq   = lane & 3;         // 0..3
    const int q0   = qt * 64;

    for (int i = tid; i < 1024; i += 256) {
        int r = i >> 4, c4 = (i & 15) * 4;
        float4 v = *(const float4*)&g_qkv[((size_t)(b * LSEQ + q0 + r)) * 1536 + h * 64 + c4];
        uint32_t* dst = (uint32_t*)&Qs[r * 68 + c4];
        dst[0] = tf32(v.x); dst[1] = tf32(v.y); dst[2] = tf32(v.z); dst[3] = tf32(v.w);
    }
    if (tid < 64) { mrow[tid] = NEGINF; lrow[tid] = 0.f; }

    float acc[4][4] = {};
    __syncthreads();

    for (int kt = 0; kt <= qt; kt++) {
        const int k0 = kt * 64;
        for (int i = tid; i < 1024; i += 256) {
            int r = i >> 4, c4 = (i & 15) * 4;
            size_t base = ((size_t)(b * LSEQ + k0 + r)) * 1536 + h * 64 + c4;
            float4 kv = *(const float4*)&g_qkv[base + 512];
            float4 vv = *(const float4*)&g_qkv[base + 1024];
            uint32_t* dk = (uint32_t*)&Ks[r * 68 + c4];
            dk[0] = tf32(kv.x); dk[1] = tf32(kv.y); dk[2] = tf32(kv.z); dk[3] = tf32(kv.w);
            uint32_t* dv = (uint32_t*)&Vs[r * 72 + c4];
            dv[0] = tf32(vv.x); dv[1] = tf32(vv.y); dv[2] = tf32(vv.z); dv[3] = tf32(vv.w);
        }
        __syncthreads();

        // S = Q @ K^T
        float s[4][4] = {};
        #pragma unroll
        for (int k8 = 0; k8 < 8; k8++) {
            const int kb = k8 * 8;
            uint32_t a0 = __float_as_uint(Qs[(wm * 16 + g    ) * 68 + kb + qq]);
            uint32_t a1 = __float_as_uint(Qs[(wm * 16 + g + 8) * 68 + kb + qq]);
            uint32_t a2 = __float_as_uint(Qs[(wm * 16 + g    ) * 68 + kb + qq + 4]);
            uint32_t a3 = __float_as_uint(Qs[(wm * 16 + g + 8) * 68 + kb + qq + 4]);
            #pragma unroll
            for (int nt = 0; nt < 4; nt++) {
                int n = wn * 32 + nt * 8 + g;
                uint32_t b0 = __float_as_uint(Ks[n * 68 + kb + qq]);
                uint32_t b1 = __float_as_uint(Ks[n * 68 + kb + qq + 4]);
                mma_tf32(s[nt], a0, a1, a2, a3, b0, b1);
            }
        }
        {
            const bool diag = (kt == qt);
            #pragma unroll
            for (int nt = 0; nt < 4; nt++) {
                int row = wm * 16 + g;
                int col = wn * 32 + nt * 8 + 2 * qq;
                float v0 = s[nt][0] * 0.125f;
                float v1 = s[nt][1] * 0.125f;
                float v2 = s[nt][2] * 0.125f;
                float v3 = s[nt][3] * 0.125f;
                if (diag) {
                    if (col     > row)     v0 = NEGINF;
                    if (col + 1 > row)     v1 = NEGINF;
                    if (col     > row + 8) v2 = NEGINF;
                    if (col + 1 > row + 8) v3 = NEGINF;
                }
                Ss[ row      * 68 + col    ] = v0;
                Ss[ row      * 68 + col + 1] = v1;
                Ss[(row + 8) * 68 + col    ] = v2;
                Ss[(row + 8) * 68 + col + 1] = v3;
            }
        }
        __syncthreads();

        // Online softmax: 4 threads per row
        {
            const int r  = tid >> 2;
            const int qj = tid & 3;
            const int c0 = qj * 16;
            float mx = NEGINF;
            #pragma unroll
            for (int c = 0; c < 16; c++) mx = fmaxf(mx, Ss[r * 68 + c0 + c]);
            mx = fmaxf(mx, __shfl_xor_sync(0xffffffffu, mx, 1));
            mx = fmaxf(mx, __shfl_xor_sync(0xffffffffu, mx, 2));
            mx = fmaxf(mx, mrow[r]);
            float sum = 0.f;
            #pragma unroll
            for (int c = 0; c < 16; c++) {
                float p = __expf(Ss[r * 68 + c0 + c] - mx);
                Ss[r * 68 + c0 + c] = __uint_as_float(tf32(p));
                sum += p;
            }
            sum += __shfl_xor_sync(0xffffffffu, sum, 1);
            sum += __shfl_xor_sync(0xffffffffu, sum, 2);
            if (qj == 0) {
                float sf = __expf(mrow[r] - mx);
                mrow[r] = mx;
                lrow[r] = lrow[r] * sf + sum;
                srow[r] = sf;
            }
        }
        __syncthreads();

        // rescale acc, then O += P @ V
        {
            float sf0 = srow[wm * 16 + g];
            float sf2 = srow[wm * 16 + g + 8];
            #pragma unroll
            for (int nt = 0; nt < 4; nt++) {
                acc[nt][0] *= sf0; acc[nt][1] *= sf0;
                acc[nt][2] *= sf2; acc[nt][3] *= sf2;
            }
        }
        #pragma unroll
        for (int k8 = 0; k8 < 8; k8++) {
            const int kb = k8 * 8;
            uint32_t a0 = __float_as_uint(Ss[(wm * 16 + g    ) * 68 + kb + qq]);
            uint32_t a1 = __float_as_uint(Ss[(wm * 16 + g + 8) * 68 + kb + qq]);
            uint32_t a2 = __float_as_uint(Ss[(wm * 16 + g    ) * 68 + kb + qq + 4]);
            uint32_t a3 = __float_as_uint(Ss[(wm * 16 + g + 8) * 68 + kb + qq + 4]);
            #pragma unroll
            for (int nt = 0; nt < 4; nt++) {
                int n = wn * 32 + nt * 8 + g;
                uint32_t b0 = __float_as_uint(Vs[(kb + qq    ) * 72 + n]);
                uint32_t b1 = __float_as_uint(Vs[(kb + qq + 4) * 72 + n]);
                mma_tf32(acc[nt], a0, a1, a2, a3, b0, b1);
            }
        }
        __syncthreads();
    }

    {
        float inv0 = 1.f / lrow[wm * 16 + g];
        float inv2 = 1.f / lrow[wm * 16 + g + 8];
        #pragma unroll
        for (int nt = 0; nt < 4; nt++) {
            int row = wm * 16 + g;
            int col = wn * 32 + nt * 8 + 2 * qq;
            float2 v0 = { acc[nt][0] * inv0, acc[nt][1] * inv0 };
            float2 v1 = { acc[nt][2] * inv2, acc[nt][3] * inv2 };
            *(float2*)&attn[((size_t)(b * LSEQ + q0 + row    )) * ET + h * 64 + col] = v0;
            *(float2*)&attn[((size_t)(b * LSEQ + q0 + row + 8)) * ET + h * 64 + col] = v1;
        }
    }
}

// ---------------------------------------------------------------------------
// Weight chain: W_all[h*64+d, n*512+e] = ((I + A_h)^{n+1} @ Wo_h)[d, e]
// ---------------------------------------------------------------------------
__global__ __launch_bounds__(256) void chain_kernel(
    const float* __restrict__ Xi, const float* __restrict__ Wo,
    float* __restrict__ wall)
{
    __shared__ float Bs[64][65];
    __shared__ float Ps[2][64][65];

    const int e0 = blockIdx.x * 64;
    const int h  = blockIdx.y;
    const int tid = threadIdx.x;
    const int tx = tid & 15;
    const int ty = tid >> 4;

    for (int i = tid; i < 64 * 64; i += 256) {
        int r = i >> 6, c = i & 63;
        float v = Xi[h * 4096 + r * 64 + c] - Xi[h * 4096 + c * 64 + r];
        if (r == c) v += 1.f;
        Bs[r][c] = v;
    }
    for (int i = tid; i < 64 * 64; i += 256) {
        int r = i >> 6, c = i & 63;
        Ps[0][r][c] = Wo[(size_t)(h * 64 + r) * EQ + e0 + c];
    }
    __syncthreads();

    int cur = 0;
    for (int m = 0; m < NF; m++) {
        float t[4][4] = {};
        #pragma unroll
        for (int d = 0; d < 64; d++) {
            float a[4], bv[4];
            #pragma unroll
            for (int i = 0; i < 4; i++) a[i]  = Bs[ty * 4 + i][d];
            #pragma unroll
            for (int j = 0; j < 4; j++) bv[j] = Ps[cur][d][tx * 4 + j];
            #pragma unroll
            for (int i = 0; i < 4; i++)
                #pragma unroll
                for (int j = 0; j < 4; j++)
                    t[i][j] += a[i] * bv[j];
        }
        #pragma unroll
        for (int i = 0; i < 4; i++) {
            int r = ty * 4 + i;
            #pragma unroll
            for (int j = 0; j < 4; j++) {
                int c = tx * 4 + j;
                Ps[1 - cur][r][c] = t[i][j];
                wall[(size_t)(h * 64 + r) * (NF * ET) + m * ET + e0 + c] = t[i][j];
            }
        }
        cur ^= 1;
        __syncthreads();
    }
}

// ---------------------------------------------------------------------------
// Launcher
// ---------------------------------------------------------------------------
extern "C" void kernel_launch(void* const* d_in, const int* in_sizes, int n_in,
                              void* d_out, int out_size)
{
    const float* query = (const float*)d_in[0];
    const float* Wqkv  = (const float*)d_in[3];
    const float* bqkv  = (const float*)d_in[4];
    const float* Wo    = (const float*)d_in[5];
    const float* bo    = (const float*)d_in[6];
    const float* Xi    = (const float*)d_in[7];
    float* out = (float*)d_out;

    float *pqkv = nullptr, *pattn = nullptr, *pwall = nullptr;
    cudaGetSymbolAddress((void**)&pqkv,  g_qkv);
    cudaGetSymbolAddress((void**)&pattn, g_attn);
    cudaGetSymbolAddress((void**)&pwall, g_wall);

    const int flash_smem = (64 * 68 * 3 + 64 * 72 + 3 * 64) * (int)sizeof(float); // 71424
    cudaFuncSetAttribute(flash_attn_tf32,
                         cudaFuncAttributeMaxDynamicSharedMemorySize, flash_smem);

    // 1) QKV projection: [8192,512] @ [512,1536] + bqkv -> g_qkv
    {
        dim3 grid((3 * ET) / 128, (NB * LSEQ) / 128);
        tgemm_db<false><<<grid, 256>>>(query, Wqkv, bqkv, pqkv,
                                       NB * LSEQ, 3 * ET, EQ, 0x7fffffff);
    }
    // 2) Causal flash attention -> g_attn [b, s, 512]
    {
        dim3 grid(LSEQ / 64, NH, NB);
        flash_attn_tf32<<<grid, 256, flash_smem>>>(pattn);
    }
    // 3) Weight chain -> g_wall [512, 4096]
    {
        dim3 grid(EQ / 64, NH);
        chain_kernel<<<grid, 256>>>(Xi, Wo, pwall);
    }
    // 4) Fused forecast+output GEMM: [8192,512] @ [512,4096] + bo -> out
    {
        dim3 grid((NF * ET) / 128, (NB * LSEQ) / 128);
        tgemm_db<true><<<grid, 256>>>(pattn, pwall, bo, out,
                                      NB * LSEQ, NF * ET, ET, 511);
    }
}

// round 15
// speedup vs baseline: 1.4252x; 1.0212x over previous
#include <cuda_runtime.h>
#include <cuda_bf16.h>
#include <cstdint>

// Problem constants
#define NB   4
#define LSEQ 2048
#define EQ   512
#define ET   512
#define NH   8
#define EH   64
#define NF   8

__device__ float g_qkv [(size_t)NB * LSEQ * 3 * ET];   // [b, s, 1536]
__device__ float g_attn[(size_t)NB * LSEQ * ET];       // [b, s, 512]
__device__ float g_wall[(size_t)ET * NF * ET];         // [512, 4096]

#define NEGINF (-1e30f)

__device__ __forceinline__ uint32_t tf32(float x) {
    uint32_t r;
    asm("cvt.rna.tf32.f32 %0, %1;" : "=r"(r) : "f"(x));
    return r;
}

__device__ __forceinline__ void mma_tf32(float* c,
    uint32_t a0, uint32_t a1, uint32_t a2, uint32_t a3,
    uint32_t b0, uint32_t b1)
{
    asm volatile(
        "mma.sync.aligned.m16n8k8.row.col.f32.tf32.tf32.f32 "
        "{%0,%1,%2,%3}, {%4,%5,%6,%7}, {%8,%9}, {%0,%1,%2,%3};"
        : "+f"(c[0]), "+f"(c[1]), "+f"(c[2]), "+f"(c[3])
        : "r"(a0), "r"(a1), "r"(a2), "r"(a3), "r"(b0), "r"(b1));
}

// ---------------------------------------------------------------------------
// tf32 GEMM, double-buffered (R12, measured 259us out / ~90us qkv).
// ---------------------------------------------------------------------------
template<bool REMAP>
__global__ __launch_bounds__(256) void tgemm_db(
    const float* __restrict__ A, const float* __restrict__ B,
    const float* __restrict__ bias, float* __restrict__ C,
    int M, int N, int K, int bias_mask)
{
    __shared__ uint32_t As[2][128][20];
    __shared__ uint32_t Bs[2][16][136];

    const int tid  = threadIdx.x;
    const int lane = tid & 31;
    const int wid  = tid >> 5;
    const int wm   = wid >> 2;
    const int wn   = wid & 3;
    const int g    = lane >> 2;
    const int qq   = lane & 3;
    const int rowBase = blockIdx.y * 128;
    const int colBase = blockIdx.x * 128;

    const int aRow = tid >> 2;
    const int aCol = (tid & 3) * 4;
    const int bRow = tid >> 5;
    const int bCol = (tid & 31) * 4;

    const float* Aptr = A + (size_t)(rowBase + aRow) * K + aCol;
    const float* Bptr = B + (size_t)bRow * N + colBase + bCol;

    float4 a0v = *(const float4*)(Aptr);
    float4 a1v = *(const float4*)(Aptr + (size_t)64 * K);
    float4 b0v = *(const float4*)(Bptr);
    float4 b1v = *(const float4*)(Bptr + (size_t)8 * N);

    {
        uint4 t;
        t.x = tf32(a0v.x); t.y = tf32(a0v.y); t.z = tf32(a0v.z); t.w = tf32(a0v.w);
        *(uint4*)&As[0][aRow][aCol] = t;
        t.x = tf32(a1v.x); t.y = tf32(a1v.y); t.z = tf32(a1v.z); t.w = tf32(a1v.w);
        *(uint4*)&As[0][64 + aRow][aCol] = t;
        t.x = tf32(b0v.x); t.y = tf32(b0v.y); t.z = tf32(b0v.z); t.w = tf32(b0v.w);
        *(uint4*)&Bs[0][bRow][bCol] = t;
        t.x = tf32(b1v.x); t.y = tf32(b1v.y); t.z = tf32(b1v.z); t.w = tf32(b1v.w);
        *(uint4*)&Bs[0][bRow + 8][bCol] = t;
    }
    __syncthreads();

    float acc[4][4][4] = {};

    for (int k0 = 0; k0 < K; k0 += 16) {
        const int p = (k0 >> 4) & 1;
        const bool more = (k0 + 16 < K);

        if (more) {
            a0v = *(const float4*)(Aptr + k0 + 16);
            a1v = *(const float4*)(Aptr + (size_t)64 * K + k0 + 16);
            b0v = *(const float4*)(Bptr + (size_t)(k0 + 16) * N);
            b1v = *(const float4*)(Bptr + (size_t)(k0 + 24) * N);
        }

        #pragma unroll
        for (int k8 = 0; k8 < 16; k8 += 8) {
            uint32_t af[4][4], bf[4][2];
            #pragma unroll
            for (int mt = 0; mt < 4; mt++) {
                int r = wm * 64 + mt * 16 + g;
                af[mt][0] = As[p][r    ][k8 + qq];
                af[mt][1] = As[p][r + 8][k8 + qq];
                af[mt][2] = As[p][r    ][k8 + qq + 4];
                af[mt][3] = As[p][r + 8][k8 + qq + 4];
            }
            #pragma unroll
            for (int nt = 0; nt < 4; nt++) {
                int n = wn * 32 + nt * 8 + g;
                bf[nt][0] = Bs[p][k8 + qq    ][n];
                bf[nt][1] = Bs[p][k8 + qq + 4][n];
            }
            #pragma unroll
            for (int mt = 0; mt < 4; mt++)
                #pragma unroll
                for (int nt = 0; nt < 4; nt++)
                    mma_tf32(acc[mt][nt], af[mt][0], af[mt][1], af[mt][2], af[mt][3],
                             bf[nt][0], bf[nt][1]);
        }

        if (more) {
            uint4 t;
            t.x = tf32(a0v.x); t.y = tf32(a0v.y); t.z = tf32(a0v.z); t.w = tf32(a0v.w);
            *(uint4*)&As[1 - p][aRow][aCol] = t;
            t.x = tf32(a1v.x); t.y = tf32(a1v.y); t.z = tf32(a1v.z); t.w = tf32(a1v.w);
            *(uint4*)&As[1 - p][64 + aRow][aCol] = t;
            t.x = tf32(b0v.x); t.y = tf32(b0v.y); t.z = tf32(b0v.z); t.w = tf32(b0v.w);
            *(uint4*)&Bs[1 - p][bRow][bCol] = t;
            t.x = tf32(b1v.x); t.y = tf32(b1v.y); t.z = tf32(b1v.z); t.w = tf32(b1v.w);
            *(uint4*)&Bs[1 - p][bRow + 8][bCol] = t;
        }
        __syncthreads();
    }

    #pragma unroll
    for (int mt = 0; mt < 4; mt++) {
        #pragma unroll
        for (int nt = 0; nt < 4; nt++) {
            int row = rowBase + wm * 64 + mt * 16 + g;
            int col = colBase + wn * 32 + nt * 8 + 2 * qq;
            float bx = bias[col & bias_mask];
            float by = bias[(col + 1) & bias_mask];
            float2 v0 = { acc[mt][nt][0] + bx, acc[mt][nt][1] + by };
            float2 v1 = { acc[mt][nt][2] + bx, acc[mt][nt][3] + by };
            size_t i0, i1;
            if (REMAP) {
                int n = col >> 9, e = col & 511;
                int b0i = row >> 11, s0i = row & 2047;
                i0 = (((size_t)(b0i * NF + n) * LSEQ + s0i) * ET) + e;
                int b1i = (row + 8) >> 11, s1i = (row + 8) & 2047;
                i1 = (((size_t)(b1i * NF + n) * LSEQ + s1i) * ET) + e;
            } else {
                i0 = (size_t)row * N + col;
                i1 = (size_t)(row + 8) * N + col;
            }
            *(float2*)&C[i0] = v0;
            *(float2*)&C[i1] = v1;
        }
    }
}

// ---------------------------------------------------------------------------
// Flash attention, Q-tile=128: one block per (q_tile=128, head, batch).
// 256 threads, 8 warps; warp (wm=wid>>1: 32 rows, wn=wid&1: 32 cols).
// K/V staging + softmax overhead amortized over 2x rows vs R6.
// ---------------------------------------------------------------------------
__global__ __launch_bounds__(256) void flash_attn_q128(float* __restrict__ attn)
{
    extern __shared__ float sm[];
    float* Qs   = sm;                    // [128][68]
    float* Ks   = Qs + 128 * 68;         // [64][68]
    float* Vs   = Ks + 64 * 68;          // [64][72]
    float* Ss   = Vs + 64 * 72;          // [128][68]
    float* mrow = Ss + 128 * 68;         // 128
    float* lrow = mrow + 128;            // 128
    float* srow = lrow + 128;            // 128

    const int qt  = blockIdx.x;          // 0..15
    const int h   = blockIdx.y;
    const int b   = blockIdx.z;
    const int tid = threadIdx.x;
    const int lane = tid & 31;
    const int wid  = tid >> 5;
    const int wm   = wid >> 1;           // 0..3 -> rows wm*32..+31
    const int wn   = wid & 1;            // 0..1 -> cols wn*32..+31
    const int g    = lane >> 2;
    const int qq   = lane & 3;
    const int q0   = qt * 128;

    // Load Q tile (128 rows, tf32): 2048 float4 groups / 256 threads = 8 iters
    for (int i = tid; i < 2048; i += 256) {
        int r = i >> 4, c4 = (i & 15) * 4;
        float4 v = *(const float4*)&g_qkv[((size_t)(b * LSEQ + q0 + r)) * 1536 + h * 64 + c4];
        uint32_t* dst = (uint32_t*)&Qs[r * 68 + c4];
        dst[0] = tf32(v.x); dst[1] = tf32(v.y); dst[2] = tf32(v.z); dst[3] = tf32(v.w);
    }
    if (tid < 128) { mrow[tid] = NEGINF; lrow[tid] = 0.f; }

    float acc[2][4][4] = {};   // [mt][nt][frag]
    __syncthreads();

    const int ktmax = 2 * qt + 1;
    for (int kt = 0; kt <= ktmax; kt++) {
        const int k0 = kt * 64;
        // Stage K, V (64 rows, tf32)
        for (int i = tid; i < 1024; i += 256) {
            int r = i >> 4, c4 = (i & 15) * 4;
            size_t base = ((size_t)(b * LSEQ + k0 + r)) * 1536 + h * 64 + c4;
            float4 kv = *(const float4*)&g_qkv[base + 512];
            float4 vv = *(const float4*)&g_qkv[base + 1024];
            uint32_t* dk = (uint32_t*)&Ks[r * 68 + c4];
            dk[0] = tf32(kv.x); dk[1] = tf32(kv.y); dk[2] = tf32(kv.z); dk[3] = tf32(kv.w);
            uint32_t* dv = (uint32_t*)&Vs[r * 72 + c4];
            dv[0] = tf32(vv.x); dv[1] = tf32(vv.y); dv[2] = tf32(vv.z); dv[3] = tf32(vv.w);
        }
        __syncthreads();

        // S = Q @ K^T : per warp 2 mt x 4 nt x 8 k8 mma
        float s[2][4][4] = {};
        #pragma unroll
        for (int k8 = 0; k8 < 8; k8++) {
            const int kb = k8 * 8;
            #pragma unroll
            for (int mt = 0; mt < 2; mt++) {
                int r0 = wm * 32 + mt * 16 + g;
                uint32_t a0 = __float_as_uint(Qs[ r0      * 68 + kb + qq]);
                uint32_t a1 = __float_as_uint(Qs[(r0 + 8) * 68 + kb + qq]);
                uint32_t a2 = __float_as_uint(Qs[ r0      * 68 + kb + qq + 4]);
                uint32_t a3 = __float_as_uint(Qs[(r0 + 8) * 68 + kb + qq + 4]);
                #pragma unroll
                for (int nt = 0; nt < 4; nt++) {
                    int n = wn * 32 + nt * 8 + g;
                    uint32_t b0 = __float_as_uint(Ks[n * 68 + kb + qq]);
                    uint32_t b1 = __float_as_uint(Ks[n * 68 + kb + qq + 4]);
                    mma_tf32(s[mt][nt], a0, a1, a2, a3, b0, b1);
                }
            }
        }
        // scale + causal mask (exact global compare on edge tiles), write S
        {
            const bool edge = (k0 + 63 > q0);   // last two kt tiles
            #pragma unroll
            for (int mt = 0; mt < 2; mt++) {
                int row = wm * 32 + mt * 16 + g;
                #pragma unroll
                for (int nt = 0; nt < 4; nt++) {
                    int col = wn * 32 + nt * 8 + 2 * qq;
                    float v0 = s[mt][nt][0] * 0.125f;
                    float v1 = s[mt][nt][1] * 0.125f;
                    float v2 = s[mt][nt][2] * 0.125f;
                    float v3 = s[mt][nt][3] * 0.125f;
                    if (edge) {
                        if (k0 + col     > q0 + row)     v0 = NEGINF;
                        if (k0 + col + 1 > q0 + row)     v1 = NEGINF;
                        if (k0 + col     > q0 + row + 8) v2 = NEGINF;
                        if (k0 + col + 1 > q0 + row + 8) v3 = NEGINF;
                    }
                    Ss[ row      * 68 + col    ] = v0;
                    Ss[ row      * 68 + col + 1] = v1;
                    Ss[(row + 8) * 68 + col    ] = v2;
                    Ss[(row + 8) * 68 + col + 1] = v3;
                }
            }
        }
        __syncthreads();

        // Online softmax: 2 threads per row (128 rows), 32 cols each
        {
            const int r    = tid >> 1;
            const int half = tid & 1;
            const int c0   = half * 32;
            float mx = NEGINF;
            #pragma unroll
            for (int c = 0; c < 32; c++) mx = fmaxf(mx, Ss[r * 68 + c0 + c]);
            mx = fmaxf(mx, __shfl_xor_sync(0xffffffffu, mx, 1));
            mx = fmaxf(mx, mrow[r]);
            float sum = 0.f;
            #pragma unroll
            for (int c = 0; c < 32; c++) {
                float p = __expf(Ss[r * 68 + c0 + c] - mx);
                Ss[r * 68 + c0 + c] = __uint_as_float(tf32(p));
                sum += p;
            }
            sum += __shfl_xor_sync(0xffffffffu, sum, 1);
            if (half == 0) {
                float sf = __expf(mrow[r] - mx);
                mrow[r] = mx;
                lrow[r] = lrow[r] * sf + sum;
                srow[r] = sf;
            }
        }
        __syncthreads();

        // rescale acc, then O += P @ V
        #pragma unroll
        for (int mt = 0; mt < 2; mt++) {
            float sf0 = srow[wm * 32 + mt * 16 + g];
            float sf2 = srow[wm * 32 + mt * 16 + g + 8];
            #pragma unroll
            for (int nt = 0; nt < 4; nt++) {
                acc[mt][nt][0] *= sf0; acc[mt][nt][1] *= sf0;
                acc[mt][nt][2] *= sf2; acc[mt][nt][3] *= sf2;
            }
        }
        #pragma unroll
        for (int k8 = 0; k8 < 8; k8++) {
            const int kb = k8 * 8;
            #pragma unroll
            for (int mt = 0; mt < 2; mt++) {
                int r0 = wm * 32 + mt * 16 + g;
                uint32_t a0 = __float_as_uint(Ss[ r0      * 68 + kb + qq]);
                uint32_t a1 = __float_as_uint(Ss[(r0 + 8) * 68 + kb + qq]);
                uint32_t a2 = __float_as_uint(Ss[ r0      * 68 + kb + qq + 4]);
                uint32_t a3 = __float_as_uint(Ss[(r0 + 8) * 68 + kb + qq + 4]);
                #pragma unroll
                for (int nt = 0; nt < 4; nt++) {
                    int n = wn * 32 + nt * 8 + g;
                    uint32_t b0 = __float_as_uint(Vs[(kb + qq    ) * 72 + n]);
                    uint32_t b1 = __float_as_uint(Vs[(kb + qq + 4) * 72 + n]);
                    mma_tf32(acc[mt][nt], a0, a1, a2, a3, b0, b1);
                }
            }
        }
        __syncthreads();
    }

    // normalize + write [b, s, h*64 + d]
    #pragma unroll
    for (int mt = 0; mt < 2; mt++) {
        int r0 = wm * 32 + mt * 16 + g;
        float inv0 = 1.f / lrow[r0];
        float inv1 = 1.f / lrow[r0 + 8];
        #pragma unroll
        for (int nt = 0; nt < 4; nt++) {
            int col = wn * 32 + nt * 8 + 2 * qq;
            float2 v0 = { acc[mt][nt][0] * inv0, acc[mt][nt][1] * inv0 };
            float2 v1 = { acc[mt][nt][2] * inv1, acc[mt][nt][3] * inv1 };
            *(float2*)&attn[((size_t)(b * LSEQ + q0 + r0    )) * ET + h * 64 + col] = v0;
            *(float2*)&attn[((size_t)(b * LSEQ + q0 + r0 + 8)) * ET + h * 64 + col] = v1;
        }
    }
}

// ---------------------------------------------------------------------------
// Weight chain: W_all[h*64+d, n*512+e] = ((I + A_h)^{n+1} @ Wo_h)[d, e]
// ---------------------------------------------------------------------------
__global__ __launch_bounds__(256) void chain_kernel(
    const float* __restrict__ Xi, const float* __restrict__ Wo,
    float* __restrict__ wall)
{
    __shared__ float Bs[64][65];
    __shared__ float Ps[2][64][65];

    const int e0 = blockIdx.x * 64;
    const int h  = blockIdx.y;
    const int tid = threadIdx.x;
    const int tx = tid & 15;
    const int ty = tid >> 4;

    for (int i = tid; i < 64 * 64; i += 256) {
        int r = i >> 6, c = i & 63;
        float v = Xi[h * 4096 + r * 64 + c] - Xi[h * 4096 + c * 64 + r];
        if (r == c) v += 1.f;
        Bs[r][c] = v;
    }
    for (int i = tid; i < 64 * 64; i += 256) {
        int r = i >> 6, c = i & 63;
        Ps[0][r][c] = Wo[(size_t)(h * 64 + r) * EQ + e0 + c];
    }
    __syncthreads();

    int cur = 0;
    for (int m = 0; m < NF; m++) {
        float t[4][4] = {};
        #pragma unroll
        for (int d = 0; d < 64; d++) {
            float a[4], bv[4];
            #pragma unroll
            for (int i = 0; i < 4; i++) a[i]  = Bs[ty * 4 + i][d];
            #pragma unroll
            for (int j = 0; j < 4; j++) bv[j] = Ps[cur][d][tx * 4 + j];
            #pragma unroll
            for (int i = 0; i < 4; i++)
                #pragma unroll
                for (int j = 0; j < 4; j++)
                    t[i][j] += a[i] * bv[j];
        }
        #pragma unroll
        for (int i = 0; i < 4; i++) {
            int r = ty * 4 + i;
            #pragma unroll
            for (int j = 0; j < 4; j++) {
                int c = tx * 4 + j;
                Ps[1 - cur][r][c] = t[i][j];
                wall[(size_t)(h * 64 + r) * (NF * ET) + m * ET + e0 + c] = t[i][j];
            }
        }
        cur ^= 1;
        __syncthreads();
    }
}

// ---------------------------------------------------------------------------
// Launcher
// ---------------------------------------------------------------------------
extern "C" void kernel_launch(void* const* d_in, const int* in_sizes, int n_in,
                              void* d_out, int out_size)
{
    const float* query = (const float*)d_in[0];
    const float* Wqkv  = (const float*)d_in[3];
    const float* bqkv  = (const float*)d_in[4];
    const float* Wo    = (const float*)d_in[5];
    const float* bo    = (const float*)d_in[6];
    const float* Xi    = (const float*)d_in[7];
    float* out = (float*)d_out;

    float *pqkv = nullptr, *pattn = nullptr, *pwall = nullptr;
    cudaGetSymbolAddress((void**)&pqkv,  g_qkv);
    cudaGetSymbolAddress((void**)&pattn, g_attn);
    cudaGetSymbolAddress((void**)&pwall, g_wall);

    // Qs(128*68) + Ks(64*68) + Vs(64*72) + Ss(128*68) + 3*128 floats
    const int flash_smem = (128 * 68 + 64 * 68 + 64 * 72 + 128 * 68 + 3 * 128)
                           * (int)sizeof(float);   // 107008 B
    cudaFuncSetAttribute(flash_attn_q128,
                         cudaFuncAttributeMaxDynamicSharedMemorySize, flash_smem);

    // 1) QKV projection: [8192,512] @ [512,1536] + bqkv -> g_qkv
    {
        dim3 grid((3 * ET) / 128, (NB * LSEQ) / 128);
        tgemm_db<false><<<grid, 256>>>(query, Wqkv, bqkv, pqkv,
                                       NB * LSEQ, 3 * ET, EQ, 0x7fffffff);
    }
    // 2) Causal flash attention (Q-tile 128) -> g_attn [b, s, 512]
    {
        dim3 grid(LSEQ / 128, NH, NB);
        flash_attn_q128<<<grid, 256, flash_smem>>>(pattn);
    }
    // 3) Weight chain -> g_wall [512, 4096]
    {
        dim3 grid(EQ / 64, NH);
        chain_kernel<<<grid, 256>>>(Xi, Wo, pwall);
    }
    // 4) Fused forecast+output GEMM: [8192,512] @ [512,4096] + bo -> out
    {
        dim3 grid((NF * ET) / 128, (NB * LSEQ) / 128);
        tgemm_db<true><<<grid, 256>>>(pattn, pwall, bo, out,
                                      NB * LSEQ, NF * ET, ET, 511);
    }
}